// round 15
// baseline (speedup 1.0000x reference)
#include <cuda_runtime.h>
#include <math.h>
#include <stdint.h>

#define Bn 1024
#define En 512
#define Nn 1024
#define Mn 64
#define Pn 70
#define EPSf 1e-16f

// scratch: z[B,N]; proj partials g_pp[b][chunk8][72]; per-b finish counter
__device__ float g_z[Bn * Nn];
__device__ float g_pp[Bn * 8 * 72];
__device__ int   g_cnt[Bn];

__device__ __forceinline__ float softplusf(float x) {
    return fmaxf(x, 0.0f) + log1pf(expf(-fabsf(x)));
}
__device__ __forceinline__ uint32_t s2u(const void* p) {
    return (uint32_t)__cvta_generic_to_shared(p);
}
__device__ __forceinline__ void mbar_init(uint32_t a, uint32_t cnt) {
    asm volatile("mbarrier.init.shared.b64 [%0], %1;" :: "r"(a), "r"(cnt) : "memory");
}
__device__ __forceinline__ void mbar_expect_tx(uint32_t a, uint32_t bytes) {
    asm volatile("mbarrier.arrive.expect_tx.shared.b64 _, [%0], %1;" :: "r"(a), "r"(bytes) : "memory");
}
__device__ __forceinline__ void mbar_arrive(uint32_t a) {
    asm volatile("mbarrier.arrive.shared.b64 _, [%0];" :: "r"(a) : "memory");
}
__device__ __forceinline__ void bulk_g2s(uint32_t dst, const void* src, uint32_t bytes, uint32_t mbar) {
    asm volatile("cp.async.bulk.shared::cta.global.mbarrier::complete_tx::bytes [%0], [%1], %2, [%3];"
                 :: "r"(dst), "l"(src), "r"(bytes), "r"(mbar) : "memory");
}
__device__ __forceinline__ void mbar_wait(uint32_t a, uint32_t parity) {
    asm volatile(
        "{\n\t.reg .pred P;\n\t"
        "W0_%=:\n\t"
        "mbarrier.try_wait.parity.acquire.cta.shared::cta.b64 P, [%0], %1, 0x989680;\n\t"
        "@P bra.uni W1_%=;\n\t"
        "bra.uni W0_%=;\n\t"
        "W1_%=:\n\t}"
        :: "r"(a), "r"(parity) : "memory");
}

// ===================== K1: proj partials, 8-way split-K + counter reset ============
__global__ __launch_bounds__(576) void proj_kernel(const float* __restrict__ emb,
                                                   const float* __restrict__ W,
                                                   const float* __restrict__ bias) {
    __shared__ float W_sh[64 * Pn];
    __shared__ float e_sh[8 * 64];

    const int tid   = threadIdx.x;
    const int group = blockIdx.x >> 3;
    const int chunk = blockIdx.x & 7;
    const int b0    = group * 8;
    const int e0    = chunk * 64;

    if (chunk == 0 && tid < 8) g_cnt[b0 + tid] = 0;   // reset handoff counters

    {
        const float4* Wv = (const float4*)(W + (size_t)e0 * Pn);
        float4* Ws = (float4*)W_sh;
        #pragma unroll 2
        for (int i = tid; i < 64 * Pn / 4; i += 576) Ws[i] = Wv[i];
        if (tid < 128) {
            int r = tid >> 4, j = tid & 15;
            ((float4*)(e_sh + r * 64))[j] =
                ((const float4*)(emb + (size_t)(b0 + r) * En + e0))[j];
        }
    }
    __syncthreads();

    if (tid < 560) {
        const int r = tid / 70, c = tid - r * 70;
        const float* er = e_sh + r * 64;
        float a0 = 0.f, a1 = 0.f, a2 = 0.f, a3 = 0.f;
        #pragma unroll 8
        for (int e = 0; e < 64; e += 4) {
            float4 ev = *(const float4*)(er + e);
            a0 = fmaf(ev.x, W_sh[(e + 0) * Pn + c], a0);
            a1 = fmaf(ev.y, W_sh[(e + 1) * Pn + c], a1);
            a2 = fmaf(ev.z, W_sh[(e + 2) * Pn + c], a2);
            a3 = fmaf(ev.w, W_sh[(e + 3) * Pn + c], a3);
        }
        float acc = (a0 + a1) + (a2 + a3);
        if (chunk == 0) acc += bias[c];
        g_pp[((size_t)(b0 + r) * 8 + chunk) * 72 + c] = acc;
    }
}

__device__ __forceinline__ float pp_sum(int b, int i) {
    const float* p = g_pp + (size_t)b * 8 * 72 + i;
    float s = 0.f;
    #pragma unroll
    for (int c = 0; c < 8; ++c) s += p[c * 72];
    return s;
}

// ===================== fused sim (quarter-b CTA) + last-finisher read ==============
// tiles 8192 floats (2 x 16KB) | k 64 | red 2 | ps 1 | flag | pad to 80 | 6 mbars
#define K2_SMEM_BYTES ((8192 + 80) * 4 + 6 * 8 + 16)

__device__ __forceinline__ float block_sum256(float v, float* red, int lane, int wid) {
    #pragma unroll
    for (int o = 16; o; o >>= 1) v += __shfl_xor_sync(0xffffffffu, v, o);
    if (lane == 0) red[wid] = v;
    __syncthreads();
    if (wid == 0) {
        float x = (lane < 8) ? red[lane] : 0.0f;
        #pragma unroll
        for (int o = 4; o; o >>= 1) x += __shfl_xor_sync(0xffffffffu, x, o);
        if (lane == 0) red[8] = x;
    }
    __syncthreads();
    return red[8];
}

__global__ __launch_bounds__(256, 6) void fused_kernel(const float* __restrict__ memory,
                                                       const float* __restrict__ w_prev,
                                                       float* __restrict__ out_md,
                                                       float* __restrict__ out_w) {
    extern __shared__ float smem[];
    float*    tiles = smem;                       // 8192 (2 x 16KB bufs)
    float*    k_sh  = smem + 8192;                // 64
    float*    redp  = k_sh + 64;                  // 2
    float*    ps    = redp + 2;                   // 1
    int*      flag  = (int*)(redp + 3);           // 1
    uint64_t* mbars = (uint64_t*)(k_sh + 80);     // full[0..3] per-tile, empty[4..5] per-buf

    const int b    = blockIdx.x >> 2;             // 4 quarter-CTAs per b
    const int q    = blockIdx.x & 3;
    const int tid  = threadIdx.x;
    const int lane = tid & 31;
    const int wid  = tid >> 5;                    // 0..7
    const float* mb = memory + ((size_t)b * Nn + q * 256) * Mn;

    const uint32_t tiles_u = s2u(tiles);
    const uint32_t mbar0   = s2u(mbars);
    // full[t] = mbar0+8t (single-use, parity 0); empty[k] = mbar0+8*(4+k), count 64

    if (tid == 0) {
        #pragma unroll
        for (int t = 0; t < 4; ++t) mbar_init(mbar0 + 8u * t, 1);
        #pragma unroll
        for (int k = 0; k < 2; ++k) mbar_init(mbar0 + 8u * (4 + k), 64);
    }
    __syncthreads();   // mbars visible

    // post first 2 tiles immediately (no backpressure) — overlaps the pp preamble
    if (tid == 255) {
        #pragma unroll
        for (int i = 0; i < 2; ++i) {
            uint32_t fb = mbar0 + 8u * i;
            mbar_expect_tx(fb, 16384);
            bulk_g2s(tiles_u + i * 16384, mb + (size_t)i * 64 * Mn, 16384, fb);
        }
    }
    if (tid < 64) {
        float v = pp_sum(b, tid);
        k_sh[tid] = v;
        float ksq = v * v;
        #pragma unroll
        for (int o = 16; o; o >>= 1) ksq += __shfl_xor_sync(0xffffffffu, ksq, o);
        if (lane == 0) redp[wid] = ksq;
    } else if (tid == 64) {
        ps[0] = pp_sum(b, 64);
    }
    __syncthreads();
    const float beta  = softplusf(ps[0]);
    const float knorm = sqrtf(redp[0] + redp[1]);

    // producer: tiles 2,3 after in-order single-use empty-waits (consumers running)
    if (tid == 255) {
        #pragma unroll
        for (int i = 2; i < 4; ++i) {
            int buf = i & 1;
            mbar_wait(mbar0 + 8u * (4 + buf), 0);     // each empty waited exactly once
            uint32_t fb = mbar0 + 8u * i;
            mbar_expect_tx(fb, 16384);
            bulk_g2s(tiles_u + buf * 16384, mb + (size_t)i * 64 * Mn, 16384, fb);
        }
    }

    // consumer: warp pair (2t,2t+1) -> tile t; thread -> one row (64 rows/tile)
    {
        const int tile = wid >> 1;
        const int row  = (wid & 1) * 32 + lane;       // 0..63 within tile
        mbar_wait(mbar0 + 8u * tile, 0);
        const float4* vrow = (const float4*)(tiles + (tile & 1) * 4096 + row * 64);
        const float4* k4   = (const float4*)k_sh;
        const int rot = lane & 15;
        float d0 = 0.f, q0 = 0.f, d1 = 0.f, q1 = 0.f;
        #pragma unroll 4
        for (int j = 0; j < 16; j += 2) {
            int j0 = (j + rot) & 15;
            int j1 = (j + 1 + rot) & 15;
            float4 kk = k4[j0];  float4 v = vrow[j0];
            float4 kk2 = k4[j1]; float4 v2 = vrow[j1];
            d0 = fmaf(kk.x, v.x, fmaf(kk.y, v.y, fmaf(kk.z, v.z, fmaf(kk.w, v.w, d0))));
            q0 = fmaf(v.x, v.x, fmaf(v.y, v.y, fmaf(v.z, v.z, fmaf(v.w, v.w, q0))));
            d1 = fmaf(kk2.x, v2.x, fmaf(kk2.y, v2.y, fmaf(kk2.z, v2.z, fmaf(kk2.w, v2.w, d1))));
            q1 = fmaf(v2.x, v2.x, fmaf(v2.y, v2.y, fmaf(v2.z, v2.z, fmaf(v2.w, v2.w, q1))));
        }
        float z = beta * (d0 + d1) / (knorm * sqrtf(q0 + q1) + EPSf);
        mbar_arrive(mbar0 + 8u * (4 + (tile & 1)));
        g_z[(size_t)b * Nn + q * 256 + tile * 64 + row] = z;
    }

    // ---- last-finisher handoff (4 quarter-CTAs per b) ----
    __threadfence();            // publish this CTA's z writes
    __syncthreads();
    if (tid == 0) {
        int old = atomicAdd(&g_cnt[b], 1);
        *flag = old;            // old==3 -> we are the last finisher
    }
    __syncthreads();
    if (*flag != 3) return;
    __threadfence();            // acquire siblings' z writes

    // ================= read phase for b (memory[b] is L2-hot) =================
    float* wg_sh = tiles;           // 1024
    float* w_sh  = tiles + 1024;    // 1024
    float* red2  = tiles + 2048;    // 9
    float* sc    = tiles + 2064;    // 5
    const float* mbf = memory + (size_t)b * Nn * Mn;

    if (tid == 0) {
        float p65 = pp_sum(b, 65);
        float a0  = pp_sum(b, 66), a1 = pp_sum(b, 67), a2 = pp_sum(b, 68);
        float p69 = pp_sum(b, 69);
        float mx = fmaxf(a0, fmaxf(a1, a2));
        float e0 = expf(a0 - mx), e1 = expf(a1 - mx), e2 = expf(a2 - mx);
        float dn = e0 + e1 + e2;
        sc[0] = 1.0f / (1.0f + expf(-p65));
        sc[1] = e0 / dn; sc[2] = e1 / dn; sc[3] = e2 / dn;
        sc[4] = 1.0f + softplusf(p69);
    }

    float4 z4  = ((const float4*)(g_z + (size_t)b * Nn))[tid];
    float4 wp4 = ((const float4*)(w_prev + (size_t)b * Nn))[tid];

    float e0 = expf(z4.x), e1 = expf(z4.y), e2 = expf(z4.z), e3 = expf(z4.w);
    float denom = block_sum256((e0 + e1) + (e2 + e3), red2, lane, wid);  // sc visible after
    float inv_d = 1.0f / denom;
    const float gg = sc[0], s0 = sc[1], s1 = sc[2], s2 = sc[3], yy = sc[4];
    float omg = 1.0f - gg;
    float wg0 = fmaf(gg, e0 * inv_d, omg * wp4.x);
    float wg1 = fmaf(gg, e1 * inv_d, omg * wp4.y);
    float wg2 = fmaf(gg, e2 * inv_d, omg * wp4.z);
    float wg3 = fmaf(gg, e3 * inv_d, omg * wp4.w);
    ((float4*)wg_sh)[tid] = make_float4(wg0, wg1, wg2, wg3);
    __syncthreads();
    float prev = wg_sh[(4 * tid - 1) & (Nn - 1)];
    float next = wg_sh[(4 * tid + 4) & (Nn - 1)];
    float wt0 = s0 * wg1 + s1 * wg0 + s2 * prev;
    float wt1 = s0 * wg2 + s1 * wg1 + s2 * wg0;
    float wt2 = s0 * wg3 + s1 * wg2 + s2 * wg1;
    float wt3 = s0 * next + s1 * wg3 + s2 * wg2;
    float p0 = __powf(wt0, yy), p1 = __powf(wt1, yy);
    float p2 = __powf(wt2, yy), p3 = __powf(wt3, yy);
    float psum = block_sum256((p0 + p1) + (p2 + p3), red2, lane, wid);
    float inv_p = 1.0f / (psum + EPSf);
    float wv0 = p0 * inv_p, wv1 = p1 * inv_p, wv2 = p2 * inv_p, wv3 = p3 * inv_p;
    ((float4*)w_sh)[tid] = make_float4(wv0, wv1, wv2, wv3);
    ((float4*)(out_w + (size_t)b * Nn))[tid] = make_float4(wv0, wv1, wv2, wv3);
    __syncthreads();

    // weighted sum over all 1024 rows (mostly L2 hits)
    const int sub = lane & 15;
    const int hh  = lane >> 4;
    float4 acc = make_float4(0.f, 0.f, 0.f, 0.f);
    #pragma unroll 4
    for (int it = 0; it < 64; ++it) {
        int n = it * 16 + wid * 2 + hh;
        float4 v = ((const float4*)(mbf + (size_t)n * Mn))[sub];
        float wn = w_sh[n];
        acc.x = fmaf(wn, v.x, acc.x);
        acc.y = fmaf(wn, v.y, acc.y);
        acc.z = fmaf(wn, v.z, acc.z);
        acc.w = fmaf(wn, v.w, acc.w);
    }
    acc.x += __shfl_xor_sync(0xffffffffu, acc.x, 16);
    acc.y += __shfl_xor_sync(0xffffffffu, acc.y, 16);
    acc.z += __shfl_xor_sync(0xffffffffu, acc.z, 16);
    acc.w += __shfl_xor_sync(0xffffffffu, acc.w, 16);
    __syncthreads();            // wg_sh shift-reads done before overwrite
    if (hh == 0)
        ((float4*)wg_sh)[wid * 16 + sub] = acc;     // partials [8][64]
    __syncthreads();
    if (tid < Mn) {
        float s = 0.0f;
        #pragma unroll
        for (int w = 0; w < 8; ++w) s += wg_sh[w * 64 + tid];
        out_md[(size_t)b * Mn + tid] = s;
    }
}

extern "C" void kernel_launch(void* const* d_in, const int* in_sizes, int n_in,
                              void* d_out, int out_size) {
    const float* embeddings = (const float*)d_in[0];   // [1024, 512]
    const float* w_prev     = (const float*)d_in[1];   // [1024, 1024]
    const float* memory     = (const float*)d_in[2];   // [1024, 1024, 64]
    const float* W          = (const float*)d_in[3];   // [512, 70]
    const float* bias       = (const float*)d_in[4];   // [70]

    float* out_md = (float*)d_out;             // memory_data [1024, 64] first
    float* out_w  = out_md + (size_t)Bn * Mn;  // then w [1024, 1024]

    proj_kernel<<<1024, 576>>>(embeddings, W, bias);
    cudaFuncSetAttribute(fused_kernel, cudaFuncAttributeMaxDynamicSharedMemorySize, K2_SMEM_BYTES);
    fused_kernel<<<4 * Bn, 256, K2_SMEM_BYTES>>>(memory, w_prev, out_md, out_w);
}

// round 17
// speedup vs baseline: 1.0411x; 1.0411x over previous
#include <cuda_runtime.h>
#include <math.h>
#include <stdint.h>

#define Bn 1024
#define En 512
#define Nn 1024
#define Mn 64
#define Pn 70
#define EPSf 1e-16f

// scratch: z[B,N]; per-b finish counter (self-resetting: last finisher writes 0)
__device__ float g_z[Bn * Nn];
__device__ int   g_cnt[Bn];

__device__ __forceinline__ float softplusf(float x) {
    return fmaxf(x, 0.0f) + log1pf(expf(-fabsf(x)));
}
__device__ __forceinline__ uint32_t s2u(const void* p) {
    return (uint32_t)__cvta_generic_to_shared(p);
}
__device__ __forceinline__ void mbar_init(uint32_t a, uint32_t cnt) {
    asm volatile("mbarrier.init.shared.b64 [%0], %1;" :: "r"(a), "r"(cnt) : "memory");
}
__device__ __forceinline__ void mbar_expect_tx(uint32_t a, uint32_t bytes) {
    asm volatile("mbarrier.arrive.expect_tx.shared.b64 _, [%0], %1;" :: "r"(a), "r"(bytes) : "memory");
}
__device__ __forceinline__ void mbar_arrive(uint32_t a) {
    asm volatile("mbarrier.arrive.shared.b64 _, [%0];" :: "r"(a) : "memory");
}
__device__ __forceinline__ void bulk_g2s(uint32_t dst, const void* src, uint32_t bytes, uint32_t mbar) {
    asm volatile("cp.async.bulk.shared::cta.global.mbarrier::complete_tx::bytes [%0], [%1], %2, [%3];"
                 :: "r"(dst), "l"(src), "r"(bytes), "r"(mbar) : "memory");
}
__device__ __forceinline__ void mbar_wait(uint32_t a, uint32_t parity) {
    asm volatile(
        "{\n\t.reg .pred P;\n\t"
        "W0_%=:\n\t"
        "mbarrier.try_wait.parity.acquire.cta.shared::cta.b64 P, [%0], %1, 0x989680;\n\t"
        "@P bra.uni W1_%=;\n\t"
        "bra.uni W0_%=;\n\t"
        "W1_%=:\n\t}"
        :: "r"(a), "r"(parity) : "memory");
}

__device__ __forceinline__ float block_sum256(float v, float* red, int lane, int wid) {
    #pragma unroll
    for (int o = 16; o; o >>= 1) v += __shfl_xor_sync(0xffffffffu, v, o);
    if (lane == 0) red[wid] = v;
    __syncthreads();
    if (wid == 0) {
        float x = (lane < 8) ? red[lane] : 0.0f;
        #pragma unroll
        for (int o = 4; o; o >>= 1) x += __shfl_xor_sync(0xffffffffu, x, o);
        if (lane == 0) red[8] = x;
    }
    __syncthreads();
    return red[8];
}

// smem floats: tiles 16384 | es 512 | pp 144 | k 64 | red 12 | sc 8 | flag 1 | pad -> mbars
#define SM_ES   16384
#define SM_PP   (SM_ES + 512)
#define SM_K    (SM_PP + 144)
#define SM_RED  (SM_K + 64)
#define SM_SC   (SM_RED + 12)
#define SM_FLAG (SM_SC + 8)
#define SM_MBAR 17128                 // 8-byte aligned float offset
#define K2_SMEM_BYTES (SM_MBAR * 4 + 12 * 8 + 16)

__global__ __launch_bounds__(256) void fused_kernel(const float* __restrict__ memory,
                                                    const float* __restrict__ emb,
                                                    const float* __restrict__ W,
                                                    const float* __restrict__ bias,
                                                    const float* __restrict__ w_prev,
                                                    float* __restrict__ out_md,
                                                    float* __restrict__ out_w) {
    extern __shared__ float smem[];
    float*    tiles = smem;                 // 16384 (4 x 16KB bufs)
    float*    es    = smem + SM_ES;         // 512
    float*    pp_sh = smem + SM_PP;         // 144
    float*    k_sh  = smem + SM_K;          // 64
    float*    redp  = smem + SM_RED;        // 12
    float*    sc    = smem + SM_SC;         // 8: beta,g,s0,s1,s2,y,knorm
    int*      flag  = (int*)(smem + SM_FLAG);
    uint64_t* mbars = (uint64_t*)(smem + SM_MBAR);   // full[0..7], empty[8..11]

    const int b    = blockIdx.x >> 1;
    const int half = blockIdx.x & 1;
    const int tid  = threadIdx.x;
    const int lane = tid & 31;
    const int wid  = tid >> 5;
    const float* mb = memory + ((size_t)b * Nn + half * 512) * Mn;

    const uint32_t tiles_u = s2u(tiles);
    const uint32_t mbar0   = s2u(mbars);

    // ---- init: mbars + emb staging, one sync ----
    if (tid == 0) {
        #pragma unroll
        for (int t = 0; t < 8; ++t) mbar_init(mbar0 + 8u * t, 1);
        #pragma unroll
        for (int k = 0; k < 4; ++k) mbar_init(mbar0 + 8u * (8 + k), 32);
    }
    if (tid < 128)
        ((float4*)es)[tid] = ((const float4*)(emb + (size_t)b * En))[tid];
    __syncthreads();

    // ---- post first 4 tiles immediately (no backpressure; overlaps inline proj) ----
    if (tid == 255) {
        #pragma unroll
        for (int i = 0; i < 4; ++i) {
            uint32_t fb = mbar0 + 8u * i;
            mbar_expect_tx(fb, 16384);
            bulk_g2s(tiles_u + i * 16384, mb + (size_t)i * 64 * Mn, 16384, fb);
        }
    }

    // ---- inline proj: 2 groups x 70 cols, 256 e each; W loads coalesced across j ----
    {
        const int h = tid >> 7;         // 0,1
        const int j = tid & 127;
        if (j < Pn) {
            const float* Wc = W + (size_t)(h * 256) * Pn + j;
            const float* er = es + h * 256;
            float a0 = 0.f, a1 = 0.f, a2 = 0.f, a3 = 0.f;
            #pragma unroll 8
            for (int e = 0; e < 256; e += 4) {
                a0 = fmaf(er[e + 0], Wc[(size_t)(e + 0) * Pn], a0);
                a1 = fmaf(er[e + 1], Wc[(size_t)(e + 1) * Pn], a1);
                a2 = fmaf(er[e + 2], Wc[(size_t)(e + 2) * Pn], a2);
                a3 = fmaf(er[e + 3], Wc[(size_t)(e + 3) * Pn], a3);
            }
            pp_sh[h * 72 + j] = (a0 + a1) + (a2 + a3);
        }
    }
    __syncthreads();
    if (tid < Pn) {
        float pr = bias[tid] + pp_sh[tid] + pp_sh[72 + tid];
        pp_sh[tid] = pr;                 // row 0 becomes final proj
        if (tid < 64) k_sh[tid] = pr;
    }
    __syncthreads();
    if (tid < 64) {
        float kv = k_sh[tid];
        float ksq = kv * kv;
        #pragma unroll
        for (int o = 16; o; o >>= 1) ksq += __shfl_xor_sync(0xffffffffu, ksq, o);
        if (lane == 0) redp[wid] = ksq;
    }
    __syncthreads();
    if (tid == 0) {
        float a0 = pp_sh[Mn + 2], a1 = pp_sh[Mn + 3], a2 = pp_sh[Mn + 4];
        float mx = fmaxf(a0, fmaxf(a1, a2));
        float e0 = expf(a0 - mx), e1 = expf(a1 - mx), e2 = expf(a2 - mx);
        float dn = e0 + e1 + e2;
        sc[0] = softplusf(pp_sh[Mn + 0]);               // beta
        sc[1] = 1.0f / (1.0f + expf(-pp_sh[Mn + 1]));   // g
        sc[2] = e0 / dn; sc[3] = e1 / dn; sc[4] = e2 / dn;
        sc[5] = 1.0f + softplusf(pp_sh[Mn + 5]);        // y
        sc[6] = sqrtf(redp[0] + redp[1]);               // k_norm
    }
    __syncthreads();
    const float beta  = sc[0];
    const float knorm = sc[6];

    // ---- producer: tiles 4-7 with in-order empty-waits (consumers now running) ----
    if (tid == 255) {
        #pragma unroll
        for (int i = 4; i < 8; ++i) {
            int buf = i & 3;
            mbar_wait(mbar0 + 8u * (8 + buf), 0);
            uint32_t fb = mbar0 + 8u * i;
            mbar_expect_tx(fb, 16384);
            bulk_g2s(tiles_u + buf * 16384, mb + (size_t)i * 64 * Mn, 16384, fb);
        }
    }

    // ---- consumer: warp wid -> tile wid (buf wid&3); thread -> rows 2*lane, 2*lane+1 ----
    {
        mbar_wait(mbar0 + 8u * wid, 0);
        const float4* va = (const float4*)(tiles + (wid & 3) * 4096) + lane * 32;
        const float4* vb = va + 16;
        const float4* k4 = (const float4*)k_sh;
        const int rot = lane & 15;
        float d0 = 0.f, q0 = 0.f, d1 = 0.f, q1 = 0.f;
        #pragma unroll 2
        for (int j = 0; j < 16; ++j) {
            int j0 = (j + rot) & 15;
            float4 kk = k4[j0];
            float4 v0 = va[j0];
            float4 v1 = vb[j0];
            d0 = fmaf(kk.x, v0.x, fmaf(kk.y, v0.y, fmaf(kk.z, v0.z, fmaf(kk.w, v0.w, d0))));
            q0 = fmaf(v0.x, v0.x, fmaf(v0.y, v0.y, fmaf(v0.z, v0.z, fmaf(v0.w, v0.w, q0))));
            d1 = fmaf(kk.x, v1.x, fmaf(kk.y, v1.y, fmaf(kk.z, v1.z, fmaf(kk.w, v1.w, d1))));
            q1 = fmaf(v1.x, v1.x, fmaf(v1.y, v1.y, fmaf(v1.z, v1.z, fmaf(v1.w, v1.w, q1))));
        }
        float z0 = beta * d0 / (knorm * sqrtf(q0) + EPSf);
        float z1 = beta * d1 / (knorm * sqrtf(q1) + EPSf);
        mbar_arrive(mbar0 + 8u * (8 + (wid & 3)));
        ((float2*)(g_z + (size_t)b * Nn + half * 512 + wid * 64))[lane] = make_float2(z0, z1);
    }

    // ---- last-finisher handoff ----
    __threadfence();            // publish this CTA's z writes
    __syncthreads();
    if (tid == 0) {
        int old = atomicAdd(&g_cnt[b], 1);
        *flag = old;            // old==1 -> last finisher
    }
    __syncthreads();
    if (*flag != 1) return;
    __threadfence();            // acquire sibling's z writes

    // ================= read phase for b (memory[b] is L2-hot) =================
    float* wg_sh = tiles;           // 1024
    float* w_sh  = tiles + 1024;    // 1024
    const float* mbf = memory + (size_t)b * Nn * Mn;

    float4 z4  = ((const float4*)(g_z + (size_t)b * Nn))[tid];
    float4 wp4 = ((const float4*)(w_prev + (size_t)b * Nn))[tid];

    float e0 = expf(z4.x), e1 = expf(z4.y), e2 = expf(z4.z), e3 = expf(z4.w);
    float denom = block_sum256((e0 + e1) + (e2 + e3), redp, lane, wid);
    float inv_d = 1.0f / denom;
    const float gg = sc[1], s0 = sc[2], s1 = sc[3], s2 = sc[4], yy = sc[5];
    float omg = 1.0f - gg;
    float wg0 = fmaf(gg, e0 * inv_d, omg * wp4.x);
    float wg1 = fmaf(gg, e1 * inv_d, omg * wp4.y);
    float wg2 = fmaf(gg, e2 * inv_d, omg * wp4.z);
    float wg3 = fmaf(gg, e3 * inv_d, omg * wp4.w);
    ((float4*)wg_sh)[tid] = make_float4(wg0, wg1, wg2, wg3);
    __syncthreads();
    float prev = wg_sh[(4 * tid - 1) & (Nn - 1)];
    float next = wg_sh[(4 * tid + 4) & (Nn - 1)];
    float wt0 = s0 * wg1 + s1 * wg0 + s2 * prev;
    float wt1 = s0 * wg2 + s1 * wg1 + s2 * wg0;
    float wt2 = s0 * wg3 + s1 * wg2 + s2 * wg1;
    float wt3 = s0 * next + s1 * wg3 + s2 * wg2;
    float p0 = __powf(wt0, yy), p1 = __powf(wt1, yy);
    float p2 = __powf(wt2, yy), p3 = __powf(wt3, yy);
    float psum = block_sum256((p0 + p1) + (p2 + p3), redp, lane, wid);
    float inv_p = 1.0f / (psum + EPSf);
    float wv0 = p0 * inv_p, wv1 = p1 * inv_p, wv2 = p2 * inv_p, wv3 = p3 * inv_p;
    ((float4*)w_sh)[tid] = make_float4(wv0, wv1, wv2, wv3);
    ((float4*)(out_w + (size_t)b * Nn))[tid] = make_float4(wv0, wv1, wv2, wv3);
    __syncthreads();

    // weighted sum over all 1024 rows (mostly L2 hits)
    const int sub = lane & 15;
    const int hh  = lane >> 4;
    float4 acc = make_float4(0.f, 0.f, 0.f, 0.f);
    #pragma unroll 4
    for (int it = 0; it < 64; ++it) {
        int n = it * 16 + wid * 2 + hh;
        float4 v = ((const float4*)(mbf + (size_t)n * Mn))[sub];
        float wn = w_sh[n];
        acc.x = fmaf(wn, v.x, acc.x);
        acc.y = fmaf(wn, v.y, acc.y);
        acc.z = fmaf(wn, v.z, acc.z);
        acc.w = fmaf(wn, v.w, acc.w);
    }
    acc.x += __shfl_xor_sync(0xffffffffu, acc.x, 16);
    acc.y += __shfl_xor_sync(0xffffffffu, acc.y, 16);
    acc.z += __shfl_xor_sync(0xffffffffu, acc.z, 16);
    acc.w += __shfl_xor_sync(0xffffffffu, acc.w, 16);
    __syncthreads();            // wg_sh shift-reads done before overwrite
    if (hh == 0)
        ((float4*)wg_sh)[wid * 16 + sub] = acc;     // partials [8][64]
    __syncthreads();
    if (tid < Mn) {
        float s = 0.0f;
        #pragma unroll
        for (int w = 0; w < 8; ++w) s += wg_sh[w * 64 + tid];
        out_md[(size_t)b * Mn + tid] = s;
    }
    if (tid == 0) g_cnt[b] = 0;   // self-reset for next graph replay
}

extern "C" void kernel_launch(void* const* d_in, const int* in_sizes, int n_in,
                              void* d_out, int out_size) {
    const float* embeddings = (const float*)d_in[0];   // [1024, 512]
    const float* w_prev     = (const float*)d_in[1];   // [1024, 1024]
    const float* memory     = (const float*)d_in[2];   // [1024, 1024, 64]
    const float* W          = (const float*)d_in[3];   // [512, 70]
    const float* bias       = (const float*)d_in[4];   // [70]

    float* out_md = (float*)d_out;             // memory_data [1024, 64] first
    float* out_w  = out_md + (size_t)Bn * Mn;  // then w [1024, 1024]

    cudaFuncSetAttribute(fused_kernel, cudaFuncAttributeMaxDynamicSharedMemorySize, K2_SMEM_BYTES);
    fused_kernel<<<2 * Bn, 256, K2_SMEM_BYTES>>>(memory, embeddings, W, bias, w_prev, out_md, out_w);
}